// round 11
// baseline (speedup 1.0000x reference)
#include <cuda_runtime.h>
#include <cstdint>

// Problem constants
#define BB 128
#define AA 8732
#define NN (BB * AA)          // 1,117,696 = 256 * 4366
#define CC 21
#define NTILES (NN / 256)     // 4366
#define TILES_PER_BLK 2
#define NBLK_MAIN (NTILES / TILES_PER_BLK)  // 2183
#define N4 (NN / 4)           // 279,424
#define BACKGROUND 0
#define TAIL_GRID 273         // 273*256*4 = 279,552 >= N4; <=296 -> resident
#define TAIL_G (TAIL_GRID * 256)

// ---------------------------------------------------------------------------
// Device scratch (static zero-init; re-zeroed at the end of every run)
// Radix levels: L1 = bits[31:24] (256), L2 = bits[23:12] (4096), L3 = bits[11:0] (4096)
// ---------------------------------------------------------------------------
__device__ unsigned int g_ce_bits[NN];
__device__ unsigned int g_h1[256];
__device__ unsigned int g_h2[4096];
__device__ unsigned int g_h3[4096];
__device__ unsigned int g_ctr[3];     // tickets: main, tail-phase1, tail-phase2
__device__ unsigned int g_phase;      // tail phase-1 -> phase-2 release flag

struct State {
    double pos_ce_sum, loc_sum, sum_gt_pre;  // sum over (v>>12) > p20
    unsigned long long num_pos, k, k_rem, cnt_above;
    unsigned int p1;                          // evolving prefix (8 -> 20 bits)
};
__device__ State g_state;             // zero-init

// ---------------------------------------------------------------------------
// Parallel descending radix-select over a histogram (block-wide broadcast).
// Precondition: 1 <= k <= total count in hist. blockDim.x == 256.
// ---------------------------------------------------------------------------
template<int BPT>
__device__ void radix_select(const unsigned int* __restrict__ hist,
                             unsigned long long k,
                             unsigned int& b_out, unsigned long long& above_out)
{
    __shared__ unsigned int ssum[256];
    __shared__ unsigned int s_b;
    __shared__ unsigned long long s_above;
    const int t = threadIdx.x;

    unsigned int cnt[BPT];
    unsigned int tsum = 0;
    #pragma unroll
    for (int j = 0; j < BPT; j++) { cnt[j] = hist[t * BPT + j]; tsum += cnt[j]; }
    ssum[t] = tsum;
    __syncthreads();
    for (int o = 1; o < 256; o <<= 1) {   // inclusive suffix scan (descending)
        unsigned int v = ssum[t] + ((t + o < 256) ? ssum[t + o] : 0u);
        __syncthreads();
        ssum[t] = v;
        __syncthreads();
    }
    unsigned long long incl  = ssum[t];
    unsigned long long above = (t < 255) ? (unsigned long long)ssum[t + 1] : 0ull;
    if (above < k && incl >= k) {         // exactly one owner thread
        unsigned long long a = above;
        int b = t * BPT;
        #pragma unroll
        for (int j = BPT - 1; j >= 0; j--) {
            unsigned long long c = cnt[j];
            if (a + c >= k) { b = t * BPT + j; break; }
            a += c;
        }
        s_b = (unsigned int)b;
        s_above = a;
    }
    __syncthreads();
    b_out = s_b;
    above_out = s_above;
}

// ---------------------------------------------------------------------------
// 1. main fused pass (unchanged from R10): 2 tiles/block, cp.async staging,
//    32 regs / 8 CTAs-SM; last block computes k and selects 8-bit prefix.
// ---------------------------------------------------------------------------
__global__ __launch_bounds__(256, 8) void main_kernel(
    const float* __restrict__ pred_loc,
    const float* __restrict__ pred_clf,
    const float* __restrict__ target_loc,
    const int*   __restrict__ target_cls)
{
    __shared__ float s_clf[256 * CC];        // 21504 B
    __shared__ unsigned int s_h[256];
    __shared__ float s_pce, s_pl1;
    __shared__ int   s_np;
    __shared__ int   s_last;
    __shared__ unsigned long long s_k;

    const int tid = threadIdx.x;
    const int lane = tid & 31;

    if (tid == 0) { s_pce = 0.f; s_pl1 = 0.f; s_np = 0; }
    s_h[tid] = 0u;

    float pce_acc = 0.f, pl1_acc = 0.f;
    int np_acc = 0;

    const unsigned int smem_clf =
        (unsigned int)__cvta_generic_to_shared(s_clf);

    const int tile0 = blockIdx.x * TILES_PER_BLK;
    #pragma unroll
    for (int t = 0; t < TILES_PER_BLK; t++) {
        const int a0 = (tile0 + t) * 256;

        __syncthreads();     // s_clf reuse: previous tile's readers done

        {
            const char* src = reinterpret_cast<const char*>(pred_clf) + (size_t)a0 * CC * 4;
            #pragma unroll
            for (int j = tid; j < (256 * CC) / 4; j += 256) {
                asm volatile("cp.async.cg.shared.global [%0], [%1], 16;\n"
                             :: "r"(smem_clf + j * 16), "l"(src + (size_t)j * 16));
            }
            asm volatile("cp.async.commit_group;\n");
        }

        const int a    = a0 + tid;
        const int tc   = target_cls[a];
        const bool pos = (tc != BACKGROUND);
        const int tcls = pos ? tc : 0;
        float l1;
        {
            const float4 pl = reinterpret_cast<const float4*>(pred_loc)[a];
            const float4 tl = reinterpret_cast<const float4*>(target_loc)[a];
            l1 = fabsf(pl.x - tl.x) + fabsf(pl.y - tl.y)
               + fabsf(pl.z - tl.z) + fabsf(pl.w - tl.w);
        }

        asm volatile("cp.async.wait_group 0;\n");
        __syncthreads();

        const float* x = s_clf + tid * CC;
        float mx = x[0];
        #pragma unroll
        for (int c = 1; c < CC; c++) mx = fmaxf(mx, x[c]);
        float se = 0.f;
        #pragma unroll
        for (int c = 0; c < CC; c++) se += __expf(x[c] - mx);
        float ce = mx + __logf(se) - x[tcls];
        ce = fmaxf(ce, 0.f);

        const unsigned int bits = pos ? 0u : __float_as_uint(ce);
        g_ce_bits[a] = bits;

        {
            const unsigned int bkt = bits >> 24;
            unsigned int mask = __match_any_sync(0xFFFFFFFFu, bkt);
            if ((int)(__ffs(mask) - 1) == lane)
                atomicAdd(&s_h[bkt], (unsigned int)__popc(mask));
        }

        if (pos) { pce_acc += ce; pl1_acc += l1; np_acc += 1; }
    }

    #pragma unroll
    for (int o = 16; o > 0; o >>= 1) {
        pce_acc += __shfl_down_sync(0xFFFFFFFFu, pce_acc, o);
        pl1_acc += __shfl_down_sync(0xFFFFFFFFu, pl1_acc, o);
        np_acc  += __shfl_down_sync(0xFFFFFFFFu, np_acc,  o);
    }
    if (lane == 0) {
        atomicAdd(&s_pce, pce_acc);
        atomicAdd(&s_pl1, pl1_acc);
        atomicAdd(&s_np,  np_acc);
    }
    __syncthreads();

    {
        unsigned int c = s_h[tid];
        if (c) atomicAdd(&g_h1[tid], c);
    }
    if (tid == 0) {
        atomicAdd(&g_state.pos_ce_sum, (double)s_pce);
        atomicAdd(&g_state.loc_sum,    (double)s_pl1);
        atomicAdd(&g_state.num_pos,    (unsigned long long)s_np);
        __threadfence();
        unsigned int prev = atomicAdd(&g_ctr[0], 1u);
        s_last = (prev == (unsigned int)gridDim.x - 1u);
    }
    __syncthreads();
    if (!s_last) return;

    if (tid == 0) {
        unsigned long long npos = g_state.num_pos;
        unsigned long long nneg = (unsigned long long)NN - npos;
        unsigned long long k = 3ull * npos;
        if (k > nneg) k = nneg;
        g_state.k = k;
        s_k = k;
    }
    __syncthreads();
    if (s_k == 0ull) {
        if (tid == 0) { g_state.p1 = 0xFFFFFFFFu; g_state.k_rem = 0ull; g_state.cnt_above = 0ull; }
        return;
    }
    unsigned int b; unsigned long long above;
    radix_select<1>(g_h1, s_k, b, above);
    if (tid == 0) {
        g_state.p1 = b;
        g_state.cnt_above = above;
        g_state.k_rem = s_k - above;   // >= 1
    }
}

// ---------------------------------------------------------------------------
// 2. tail: fused refine + final with internal grid-wide barrier.
//    273 resident blocks; g_ce_bits is L2-hot; MLP=4 predicated loads.
// ---------------------------------------------------------------------------
__global__ __launch_bounds__(256) void tail_kernel(float* __restrict__ out) {
    __shared__ unsigned int s_h[4096];   // 16 KB, reused across phases
    __shared__ double sh[8];
    __shared__ int s_last;

    const int tid = threadIdx.x;
    const int wid = tid >> 5, lid = tid & 31;
    const uint4* cb = reinterpret_cast<const uint4*>(g_ce_bits);
    volatile State* vs = (volatile State*)&g_state;

    const int base = blockIdx.x * 256 + tid;
    const int i1 = base + TAIL_G, i2 = base + 2 * TAIL_G, i3 = base + 3 * TAIL_G;
    const bool b0 = base < N4, b1 = i1 < N4, b2 = i2 < N4, b3 = i3 < N4;

    // ================= phase 1: bits[23:12] hist within 8-bit prefix ========
    for (int j = tid; j < 4096; j += 256) s_h[j] = 0u;
    __syncthreads();

    const unsigned int p1 = vs->p1;         // sentinel matches nothing
    {
        uint4 v0, v1v, v2v, v3v;            // 4 independent loads (MLP=4)
        if (b0) v0  = cb[base];
        if (b1) v1v = cb[i1];
        if (b2) v2v = cb[i2];
        if (b3) v3v = cb[i3];
        #define P1W(w) if (((w) >> 24) == p1) atomicAdd(&s_h[((w) >> 12) & 0xFFFu], 1u)
        if (b0) { P1W(v0.x);  P1W(v0.y);  P1W(v0.z);  P1W(v0.w);  }
        if (b1) { P1W(v1v.x); P1W(v1v.y); P1W(v1v.z); P1W(v1v.w); }
        if (b2) { P1W(v2v.x); P1W(v2v.y); P1W(v2v.z); P1W(v2v.w); }
        if (b3) { P1W(v3v.x); P1W(v3v.y); P1W(v3v.z); P1W(v3v.w); }
        #undef P1W
    }
    __syncthreads();
    for (int j = tid; j < 4096; j += 256) {
        unsigned int c = s_h[j];
        if (c) atomicAdd(&g_h2[j], c);
    }
    if (tid == 0) {
        __threadfence();
        unsigned int prev = atomicAdd(&g_ctr[1], 1u);
        s_last = (prev == (unsigned int)gridDim.x - 1u);
    }
    __syncthreads();

    if (s_last) {
        unsigned long long kr = vs->k_rem;
        if (kr != 0ull) {
            unsigned int b; unsigned long long above;
            radix_select<16>(g_h2, kr, b, above);
            if (tid == 0) {
                g_state.p1 = (vs->p1 << 12) | b;  // 20-bit prefix
                g_state.cnt_above = vs->cnt_above + above;
                g_state.k_rem = kr - above;
            }
        }
        if (tid == 0) {
            __threadfence();
            atomicExch(&g_phase, 1u);    // release all blocks
        }
    }
    // grid-wide barrier: thread 0 spins, everyone else waits at the bar
    if (tid == 0) {
        while (atomicAdd(&g_phase, 0u) == 0u) __nanosleep(64);
    }
    __syncthreads();

    // ================= phase 2: L3 counts + above-prefix sum ================
    for (int j = tid; j < 4096; j += 256) s_h[j] = 0u;
    __syncthreads();

    const unsigned int p20 = vs->p1;        // 20-bit prefix (or sentinel)
    double gt = 0.0;
    {
        uint4 v0, v1v, v2v, v3v;
        if (b0) v0  = cb[base];
        if (b1) v1v = cb[i1];
        if (b2) v2v = cb[i2];
        if (b3) v3v = cb[i3];
        #define P2W(w) { unsigned int h = (w) >> 12; \
            if (h > p20) gt += (double)__uint_as_float(w); \
            else if (h == p20) atomicAdd(&s_h[(w) & 0xFFFu], 1u); }
        if (b0) { P2W(v0.x)  P2W(v0.y)  P2W(v0.z)  P2W(v0.w)  }
        if (b1) { P2W(v1v.x) P2W(v1v.y) P2W(v1v.z) P2W(v1v.w) }
        if (b2) { P2W(v2v.x) P2W(v2v.y) P2W(v2v.z) P2W(v2v.w) }
        if (b3) { P2W(v3v.x) P2W(v3v.y) P2W(v3v.z) P2W(v3v.w) }
        #undef P2W
    }
    #pragma unroll
    for (int o = 16; o > 0; o >>= 1)
        gt += __shfl_down_sync(0xFFFFFFFFu, gt, o);
    if (lid == 0) sh[wid] = gt;
    __syncthreads();
    for (int j = tid; j < 4096; j += 256) {
        unsigned int c = s_h[j];
        if (c) atomicAdd(&g_h3[j], c);
    }
    if (tid == 0) {
        double b = 0.0;
        #pragma unroll
        for (int w = 0; w < 8; w++) b += sh[w];
        atomicAdd(&g_state.sum_gt_pre, b);
        __threadfence();
        unsigned int prev = atomicAdd(&g_ctr[2], 1u);
        s_last = (prev == (unsigned int)gridDim.x - 1u);
    }
    __syncthreads();
    if (!s_last) return;

    // ---- last block: select final bucket, finalize, re-zero ----
    {
        const unsigned long long kr = vs->k_rem;
        const double np = (double)vs->num_pos;
        const double kk = (double)vs->k;

        if (kr == 0ull) {
            if (tid == 0) {
                out[0] = (float)(vs->pos_ce_sum / (np + kk));
                out[1] = (float)(vs->loc_sum / np);
            }
        } else {
            unsigned int b; unsigned long long above;
            radix_select<16>(g_h3, kr, b, above);
            // analytic tail: each L3 bucket holds identical 32-bit values
            double tail = 0.0;
            #pragma unroll
            for (int j = 0; j < 16; j++) {
                int idx = tid * 16 + j;
                if (idx > (int)b) {
                    unsigned int c = g_h3[idx];
                    if (c) tail += (double)c *
                        (double)__uint_as_float((p20 << 12) | (unsigned int)idx);
                }
            }
            #pragma unroll
            for (int o = 16; o > 0; o >>= 1)
                tail += __shfl_down_sync(0xFFFFFFFFu, tail, o);
            if (lid == 0) sh[wid] = tail;
            __syncthreads();
            if (tid == 0) {
                double t2 = 0.0;
                #pragma unroll
                for (int w = 0; w < 8; w++) t2 += sh[w];
                const unsigned int thresh = (p20 << 12) | b;
                const unsigned long long cnt_gt = vs->cnt_above + above;
                const unsigned long long ties = vs->k - cnt_gt;
                const double tval = (double)__uint_as_float(thresh);
                const double topk = vs->sum_gt_pre + t2 + (double)ties * tval;
                out[0] = (float)((vs->pos_ce_sum + topk) / (np + kk));
                out[1] = (float)(vs->loc_sum / np);
            }
        }
    }
    __syncthreads();
    // re-zero scratch for the next graph replay
    for (int j = tid; j < 4096; j += 256) { g_h2[j] = 0u; g_h3[j] = 0u; }
    if (tid < 256) g_h1[tid] = 0u;
    if (tid < 3)   g_ctr[tid] = 0u;
    if (tid == 0) {
        g_phase = 0u;
        g_state.pos_ce_sum = 0.0; g_state.loc_sum = 0.0; g_state.sum_gt_pre = 0.0;
        g_state.num_pos = 0ull; g_state.k = 0ull; g_state.k_rem = 0ull;
        g_state.cnt_above = 0ull;
        g_state.p1 = 0xFFFFFFFFu;
    }
}

// ---------------------------------------------------------------------------
// launch: 2 kernels total
// ---------------------------------------------------------------------------
extern "C" void kernel_launch(void* const* d_in, const int* in_sizes, int n_in,
                              void* d_out, int out_size)
{
    const float* pred_loc   = (const float*)d_in[0];
    const float* pred_clf   = (const float*)d_in[1];
    const float* target_loc = (const float*)d_in[2];
    const int*   target_cls = (const int*)  d_in[3];
    float* out = (float*)d_out;

    main_kernel<<<NBLK_MAIN, 256>>>(pred_loc, pred_clf, target_loc, target_cls);
    tail_kernel<<<TAIL_GRID, 256>>>(out);
}

// round 13
// speedup vs baseline: 1.0029x; 1.0029x over previous
#include <cuda_runtime.h>
#include <cstdint>

// Problem constants
#define BB 128
#define AA 8732
#define NN (BB * AA)          // 1,117,696 = 256 * 4366
#define CC 21
#define NTILES (NN / 256)     // 4366
#define TILES_PER_BLK 2
#define NBLK_MAIN (NTILES / TILES_PER_BLK)  // 2183
#define N4 (NN / 4)           // 279,424
#define BACKGROUND 0
#define TGRID 1092            // 1092*256 = 279,552 >= N4

// ---------------------------------------------------------------------------
// Device scratch (static zero-init; re-zeroed at the end of every run)
// Radix levels: L1 = bits[31:20] (4096), L2 = bits[19:8] (4096), L3 = bits[7:0] (256)
// ---------------------------------------------------------------------------
__device__ unsigned int g_ce_bits[NN];
__device__ unsigned int g_h1[4096];
__device__ unsigned int g_h2[4096];
__device__ unsigned int g_h3[256];
__device__ unsigned int g_ctr[3];     // tickets: main, tail1, tail2

struct State {
    double pos_ce_sum, loc_sum, sum_gt_pre;  // sum over (v>>8) > p24
    unsigned long long num_pos, k, k_rem, cnt_above;
    unsigned int p1;                          // evolving prefix (12 -> 24 bits)
};
__device__ State g_state;             // zero-init

// ---------------------------------------------------------------------------
// Parallel descending radix-select over a histogram (block-wide broadcast).
// Precondition: 1 <= k <= total count in hist. blockDim.x == 256.
// ---------------------------------------------------------------------------
template<int BPT>
__device__ void radix_select(const unsigned int* __restrict__ hist,
                             unsigned long long k,
                             unsigned int& b_out, unsigned long long& above_out)
{
    __shared__ unsigned int ssum[256];
    __shared__ unsigned int s_b;
    __shared__ unsigned long long s_above;
    const int t = threadIdx.x;

    unsigned int cnt[BPT];
    unsigned int tsum = 0;
    #pragma unroll
    for (int j = 0; j < BPT; j++) { cnt[j] = hist[t * BPT + j]; tsum += cnt[j]; }
    ssum[t] = tsum;
    __syncthreads();
    for (int o = 1; o < 256; o <<= 1) {   // inclusive suffix scan (descending)
        unsigned int v = ssum[t] + ((t + o < 256) ? ssum[t + o] : 0u);
        __syncthreads();
        ssum[t] = v;
        __syncthreads();
    }
    unsigned long long incl  = ssum[t];
    unsigned long long above = (t < 255) ? (unsigned long long)ssum[t + 1] : 0ull;
    if (above < k && incl >= k) {         // exactly one owner thread
        unsigned long long a = above;
        int b = t * BPT;
        #pragma unroll
        for (int j = BPT - 1; j >= 0; j--) {
            unsigned long long c = cnt[j];
            if (a + c >= k) { b = t * BPT + j; break; }
            a += c;
        }
        s_b = (unsigned int)b;
        s_above = a;
    }
    __syncthreads();
    b_out = s_b;
    above_out = s_above;
}

// warp-aggregated global histogram add (leader of each matching subset adds)
__device__ __forceinline__ void agg_gatom(unsigned int* hist, unsigned int bkt) {
    unsigned int m = __match_any_sync(__activemask(), bkt);
    if ((int)(__ffs(m) - 1) == (int)(threadIdx.x & 31))
        atomicAdd(&hist[bkt], (unsigned int)__popc(m));
}

// ---------------------------------------------------------------------------
// 1. main fused pass: 2 tiles/block, cp.async staging; 12-bit L1 histogram
//    (4096 buckets, shared-privatized); last block computes k, selects p12.
// ---------------------------------------------------------------------------
__global__ __launch_bounds__(256, 6) void main_kernel(
    const float* __restrict__ pred_loc,
    const float* __restrict__ pred_clf,
    const float* __restrict__ target_loc,
    const int*   __restrict__ target_cls)
{
    __shared__ float s_clf[256 * CC];        // 21504 B
    __shared__ unsigned int s_h[4096];       // 16384 B
    __shared__ float s_pce, s_pl1;
    __shared__ int   s_np;
    __shared__ int   s_last;
    __shared__ unsigned long long s_k;

    const int tid = threadIdx.x;
    const int lane = tid & 31;

    if (tid == 0) { s_pce = 0.f; s_pl1 = 0.f; s_np = 0; }
    for (int j = tid; j < 4096; j += 256) s_h[j] = 0u;

    float pce_acc = 0.f, pl1_acc = 0.f;
    int np_acc = 0;

    const unsigned int smem_clf =
        (unsigned int)__cvta_generic_to_shared(s_clf);

    const int tile0 = blockIdx.x * TILES_PER_BLK;
    #pragma unroll
    for (int t = 0; t < TILES_PER_BLK; t++) {
        const int a0 = (tile0 + t) * 256;

        __syncthreads();     // s_clf reuse: previous tile's readers done

        {
            const char* src = reinterpret_cast<const char*>(pred_clf) + (size_t)a0 * CC * 4;
            #pragma unroll
            for (int j = tid; j < (256 * CC) / 4; j += 256) {
                asm volatile("cp.async.cg.shared.global [%0], [%1], 16;\n"
                             :: "r"(smem_clf + j * 16), "l"(src + (size_t)j * 16));
            }
            asm volatile("cp.async.commit_group;\n");
        }

        const int a    = a0 + tid;
        const int tc   = target_cls[a];
        const bool pos = (tc != BACKGROUND);
        const int tcls = pos ? tc : 0;
        float l1;
        {
            const float4 pl = reinterpret_cast<const float4*>(pred_loc)[a];
            const float4 tl = reinterpret_cast<const float4*>(target_loc)[a];
            l1 = fabsf(pl.x - tl.x) + fabsf(pl.y - tl.y)
               + fabsf(pl.z - tl.z) + fabsf(pl.w - tl.w);
        }

        asm volatile("cp.async.wait_group 0;\n");
        __syncthreads();

        const float* x = s_clf + tid * CC;
        float mx = x[0];
        #pragma unroll
        for (int c = 1; c < CC; c++) mx = fmaxf(mx, x[c]);
        float se = 0.f;
        #pragma unroll
        for (int c = 0; c < CC; c++) se += __expf(x[c] - mx);
        float ce = mx + __logf(se) - x[tcls];
        ce = fmaxf(ce, 0.f);

        const unsigned int bits = pos ? 0u : __float_as_uint(ce);
        g_ce_bits[a] = bits;

        // warp-aggregated 12-bit histogram update
        {
            const unsigned int bkt = bits >> 20;
            unsigned int mask = __match_any_sync(0xFFFFFFFFu, bkt);
            if ((int)(__ffs(mask) - 1) == lane)
                atomicAdd(&s_h[bkt], (unsigned int)__popc(mask));
        }

        if (pos) { pce_acc += ce; pl1_acc += l1; np_acc += 1; }
    }

    #pragma unroll
    for (int o = 16; o > 0; o >>= 1) {
        pce_acc += __shfl_down_sync(0xFFFFFFFFu, pce_acc, o);
        pl1_acc += __shfl_down_sync(0xFFFFFFFFu, pl1_acc, o);
        np_acc  += __shfl_down_sync(0xFFFFFFFFu, np_acc,  o);
    }
    if (lane == 0) {
        atomicAdd(&s_pce, pce_acc);
        atomicAdd(&s_pl1, pl1_acc);
        atomicAdd(&s_np,  np_acc);
    }
    __syncthreads();

    for (int j = tid; j < 4096; j += 256) {
        unsigned int c = s_h[j];
        if (c) atomicAdd(&g_h1[j], c);
    }
    if (tid == 0) {
        atomicAdd(&g_state.pos_ce_sum, (double)s_pce);
        atomicAdd(&g_state.loc_sum,    (double)s_pl1);
        atomicAdd(&g_state.num_pos,    (unsigned long long)s_np);
        __threadfence();
        unsigned int prev = atomicAdd(&g_ctr[0], 1u);
        s_last = (prev == (unsigned int)gridDim.x - 1u);
    }
    __syncthreads();
    if (!s_last) return;

    // ---- last block: compute k, select 12-bit prefix ----
    volatile State* vs = (volatile State*)&g_state;
    if (tid == 0) {
        unsigned long long npos = vs->num_pos;
        unsigned long long nneg = (unsigned long long)NN - npos;
        unsigned long long k = 3ull * npos;
        if (k > nneg) k = nneg;
        g_state.k = k;
        s_k = k;
    }
    __syncthreads();
    if (s_k == 0ull) {
        if (tid == 0) { g_state.p1 = 0xFFFFFFFFu; g_state.k_rem = 0ull; g_state.cnt_above = 0ull; }
        return;
    }
    unsigned int b; unsigned long long above;
    radix_select<16>(g_h1, s_k, b, above);
    if (tid == 0) {
        g_state.p1 = b;
        g_state.cnt_above = above;
        g_state.k_rem = s_k - above;   // >= 1
    }
}

// ---------------------------------------------------------------------------
// 2. tail1: bits[19:8] hist within 12-bit prefix (warp-aggregated global
//    atomics; low match rate); last block extends prefix to 24 bits.
// ---------------------------------------------------------------------------
__global__ __launch_bounds__(256) void tail1_kernel() {
    __shared__ int s_last;
    const int tid = threadIdx.x;
    volatile State* vs = (volatile State*)&g_state;

    const unsigned int p12 = vs->p1;        // sentinel matches nothing
    const int i = blockIdx.x * 256 + tid;
    if (i < N4) {
        uint4 v = reinterpret_cast<const uint4*>(g_ce_bits)[i];
        if ((v.x >> 20) == p12) agg_gatom(g_h2, (v.x >> 8) & 0xFFFu);
        if ((v.y >> 20) == p12) agg_gatom(g_h2, (v.y >> 8) & 0xFFFu);
        if ((v.z >> 20) == p12) agg_gatom(g_h2, (v.z >> 8) & 0xFFFu);
        if ((v.w >> 20) == p12) agg_gatom(g_h2, (v.w >> 8) & 0xFFFu);
    }
    if (tid == 0) {
        __threadfence();
        unsigned int prev = atomicAdd(&g_ctr[1], 1u);
        s_last = (prev == (unsigned int)gridDim.x - 1u);
    }
    __syncthreads();
    if (!s_last) return;

    unsigned long long kr = vs->k_rem;
    if (kr == 0ull) return;                  // k==0: sentinel prefix stays
    unsigned int b; unsigned long long above;
    radix_select<16>(g_h2, kr, b, above);
    if (tid == 0) {
        g_state.p1 = (vs->p1 << 12) | b;     // 24-bit prefix
        g_state.cnt_above = vs->cnt_above + above;
        g_state.k_rem = kr - above;
    }
}

// ---------------------------------------------------------------------------
// 3. tail2: low-8 counts within 24-bit prefix (few matches) + sum of
//    strictly-above-prefix values; last block selects exact threshold,
//    reconstructs tail analytically (bucket == identical 32-bit value),
//    finalizes, re-zeros.
// ---------------------------------------------------------------------------
__global__ __launch_bounds__(256) void tail2_kernel(float* __restrict__ out) {
    __shared__ double sh[8];
    __shared__ int s_last;
    const int tid = threadIdx.x;
    const int wid = tid >> 5, lid = tid & 31;
    volatile State* vs = (volatile State*)&g_state;

    const unsigned int p24 = vs->p1;        // 24-bit prefix (or sentinel)
    double gt = 0.0;
    const int i = blockIdx.x * 256 + tid;
    if (i < N4) {
        uint4 v = reinterpret_cast<const uint4*>(g_ce_bits)[i];
        unsigned int h;
        h = v.x >> 8; if (h > p24) gt += (double)__uint_as_float(v.x); else if (h == p24) agg_gatom(g_h3, v.x & 0xFFu);
        h = v.y >> 8; if (h > p24) gt += (double)__uint_as_float(v.y); else if (h == p24) agg_gatom(g_h3, v.y & 0xFFu);
        h = v.z >> 8; if (h > p24) gt += (double)__uint_as_float(v.z); else if (h == p24) agg_gatom(g_h3, v.z & 0xFFu);
        h = v.w >> 8; if (h > p24) gt += (double)__uint_as_float(v.w); else if (h == p24) agg_gatom(g_h3, v.w & 0xFFu);
    }
    #pragma unroll
    for (int o = 16; o > 0; o >>= 1)
        gt += __shfl_down_sync(0xFFFFFFFFu, gt, o);
    if (lid == 0) sh[wid] = gt;
    __syncthreads();
    if (tid == 0) {
        double b = 0.0;
        #pragma unroll
        for (int w = 0; w < 8; w++) b += sh[w];
        if (b != 0.0) atomicAdd(&g_state.sum_gt_pre, b);
        __threadfence();
        unsigned int prev = atomicAdd(&g_ctr[2], 1u);
        s_last = (prev == (unsigned int)gridDim.x - 1u);
    }
    __syncthreads();
    if (!s_last) return;

    // ---- last block: final select + output + re-zero ----
    {
        const unsigned long long kr = vs->k_rem;
        const double np = (double)vs->num_pos;
        const double kk = (double)vs->k;

        if (kr == 0ull) {                   // k == 0 overall
            if (tid == 0) {
                out[0] = (float)(vs->pos_ce_sum / (np + kk));
                out[1] = (float)(vs->loc_sum / np);
            }
        } else {
            unsigned int b; unsigned long long above;
            radix_select<1>(g_h3, kr, b, above);
            // analytic tail: each low-8 bucket holds one identical 32-bit value
            double tail = 0.0;
            if (tid > (int)b) {
                unsigned int c = g_h3[tid];
                if (c) tail = (double)c *
                    (double)__uint_as_float((p24 << 8) | (unsigned int)tid);
            }
            #pragma unroll
            for (int o = 16; o > 0; o >>= 1)
                tail += __shfl_down_sync(0xFFFFFFFFu, tail, o);
            if (lid == 0) sh[wid] = tail;
            __syncthreads();
            if (tid == 0) {
                double t2 = 0.0;
                #pragma unroll
                for (int w = 0; w < 8; w++) t2 += sh[w];
                const unsigned int thresh = (p24 << 8) | b;
                const unsigned long long cnt_gt = vs->cnt_above + above;
                const unsigned long long ties = vs->k - cnt_gt;
                const double tval = (double)__uint_as_float(thresh);
                const double topk = vs->sum_gt_pre + t2 + (double)ties * tval;
                out[0] = (float)((vs->pos_ce_sum + topk) / (np + kk));
                out[1] = (float)(vs->loc_sum / np);
            }
        }
    }
    __syncthreads();
    // re-zero scratch for the next graph replay
    for (int j = tid; j < 4096; j += 256) { g_h1[j] = 0u; g_h2[j] = 0u; }
    if (tid < 256) g_h3[tid] = 0u;
    if (tid < 3)   g_ctr[tid] = 0u;
    if (tid == 0) {
        g_state.pos_ce_sum = 0.0; g_state.loc_sum = 0.0; g_state.sum_gt_pre = 0.0;
        g_state.num_pos = 0ull; g_state.k = 0ull; g_state.k_rem = 0ull;
        g_state.cnt_above = 0ull;
        g_state.p1 = 0xFFFFFFFFu;
    }
}

// ---------------------------------------------------------------------------
// launch: 3 kernels total
// ---------------------------------------------------------------------------
extern "C" void kernel_launch(void* const* d_in, const int* in_sizes, int n_in,
                              void* d_out, int out_size)
{
    const float* pred_loc   = (const float*)d_in[0];
    const float* pred_clf   = (const float*)d_in[1];
    const float* target_loc = (const float*)d_in[2];
    const int*   target_cls = (const int*)  d_in[3];
    float* out = (float*)d_out;

    main_kernel<<<NBLK_MAIN, 256>>>(pred_loc, pred_clf, target_loc, target_cls);
    tail1_kernel<<<TGRID, 256>>>();
    tail2_kernel<<<TGRID, 256>>>(out);
}